// round 1
// baseline (speedup 1.0000x reference)
#include <cuda_runtime.h>

// CosinLoss: loss = mean_i( 1 - dot(pc_i, aug_i) / (max(||pc_i||,eps) * max(||aug_i||,eps)) )
// N = 16384 rows, D = 1024 fp32. Pure HBM-streaming reduction (128 MiB read).

#define CL_N 16384
#define CL_D 1024
#define CL_EPS 1e-12f

// Per-row loss scratch (device global: no allocation allowed in kernel_launch).
__device__ float g_row_loss[CL_N];

// Kernel 1: one CTA per row. 256 threads x float4 = 1024 floats per tensor.
__global__ __launch_bounds__(256, 8)
void row_cos_kernel(const float* __restrict__ pc, const float* __restrict__ aug) {
    const int row = blockIdx.x;
    const int t   = threadIdx.x;

    const float4* __restrict__ p4 = reinterpret_cast<const float4*>(pc  + (size_t)row * CL_D);
    const float4* __restrict__ a4 = reinterpret_cast<const float4*>(aug + (size_t)row * CL_D);

    float4 p = p4[t];
    float4 a = a4[t];

    float dot = p.x * a.x + p.y * a.y + p.z * a.z + p.w * a.w;
    float npp = p.x * p.x + p.y * p.y + p.z * p.z + p.w * p.w;
    float naa = a.x * a.x + a.y * a.y + a.z * a.z + a.w * a.w;

    // Warp reduce (3 values)
    #pragma unroll
    for (int off = 16; off > 0; off >>= 1) {
        dot += __shfl_down_sync(0xFFFFFFFFu, dot, off);
        npp += __shfl_down_sync(0xFFFFFFFFu, npp, off);
        naa += __shfl_down_sync(0xFFFFFFFFu, naa, off);
    }

    __shared__ float s_dot[8], s_npp[8], s_naa[8];
    const int wid = t >> 5;
    const int lid = t & 31;
    if (lid == 0) {
        s_dot[wid] = dot;
        s_npp[wid] = npp;
        s_naa[wid] = naa;
    }
    __syncthreads();

    if (wid == 0) {
        dot = (lid < 8) ? s_dot[lid] : 0.0f;
        npp = (lid < 8) ? s_npp[lid] : 0.0f;
        naa = (lid < 8) ? s_naa[lid] : 0.0f;
        #pragma unroll
        for (int off = 4; off > 0; off >>= 1) {
            dot += __shfl_down_sync(0xFFFFFFFFu, dot, off);
            npp += __shfl_down_sync(0xFFFFFFFFu, npp, off);
            naa += __shfl_down_sync(0xFFFFFFFFu, naa, off);
        }
        if (lid == 0) {
            float np_ = fmaxf(sqrtf(npp), CL_EPS);
            float na_ = fmaxf(sqrtf(naa), CL_EPS);
            g_row_loss[row] = 1.0f - dot / (np_ * na_);
        }
    }
}

// Kernel 2: single CTA reduces 16384 per-row losses -> mean -> d_out[0].
__global__ __launch_bounds__(1024)
void reduce_kernel(float* __restrict__ out) {
    const int t = threadIdx.x;
    const float4* __restrict__ v4 = reinterpret_cast<const float4*>(g_row_loss);

    float s = 0.0f;
    // 16384 floats = 4096 float4; 1024 threads x 4 float4 each
    #pragma unroll
    for (int i = 0; i < 4; i++) {
        float4 v = v4[t + i * 1024];
        s += (v.x + v.y) + (v.z + v.w);
    }

    #pragma unroll
    for (int off = 16; off > 0; off >>= 1)
        s += __shfl_down_sync(0xFFFFFFFFu, s, off);

    __shared__ float s_sum[32];
    const int wid = t >> 5;
    const int lid = t & 31;
    if (lid == 0) s_sum[wid] = s;
    __syncthreads();

    if (wid == 0) {
        s = (lid < 32) ? s_sum[lid] : 0.0f;
        #pragma unroll
        for (int off = 16; off > 0; off >>= 1)
            s += __shfl_down_sync(0xFFFFFFFFu, s, off);
        if (lid == 0)
            out[0] = s * (1.0f / (float)CL_N);
    }
}

extern "C" void kernel_launch(void* const* d_in, const int* in_sizes, int n_in,
                              void* d_out, int out_size) {
    const float* pc  = (const float*)d_in[0];
    const float* aug = (const float*)d_in[1];
    float* out = (float*)d_out;

    row_cos_kernel<<<CL_N, 256>>>(pc, aug);
    reduce_kernel<<<1, 1024>>>(out);
}